// round 7
// baseline (speedup 1.0000x reference)
#include <cuda_runtime.h>

#define T_TOTAL 262144
#define NF 64
#define ROWS 32
#define XR4  (NF / 4)        // x row stride in float4 (16)
#define OR4  (4 * NF / 4)    // out row stride in float4 (64)
#define TILES_PER_BLOCK 8    // 128 threads, 16 threads per tile

__device__ __forceinline__ float4 f4add(float4 a, float4 b) {
    return make_float4(a.x + b.x, a.y + b.y, a.z + b.z, a.w + b.w);
}
__device__ __forceinline__ float4 f4sub(float4 a, float4 b) {
    return make_float4(a.x - b.x, a.y - b.y, a.z - b.z, a.w - b.w);
}
__device__ __forceinline__ float4 f4scale(float4 a, float s) {
    return make_float4(a.x * s, a.y * s, a.z * s, a.w * s);
}

__global__ void __launch_bounds__(128, 10)
ma_kernel(const float* __restrict__ x, float* __restrict__ out) {
    const int t    = threadIdx.x;
    const int c    = t & 15;                        // column group (4 cols each)
    const int tile = blockIdx.x * TILES_PER_BLOCK + (t >> 4);
    const int r0   = tile * ROWS;

    const float4* xc = (const float4*)x + c;        // stride XR4 per row
    float4*       oc = (float4*)out + c;            // stride OR4 per row

    float4 s7  = make_float4(0.f, 0.f, 0.f, 0.f);
    float4 s30 = s7, s90 = s7;

    // Halo: up to 90 rows above this tile (rows < 0 are implicit zeros).
    {
        int kmax = (r0 < 90) ? r0 : 90;
        #pragma unroll 6
        for (int k = 1; k <= kmax; k++) {
            float4 v = __ldcg(&xc[(r0 - k) * XR4]);
            s90 = f4add(s90, v);
            if (k <= 30) s30 = f4add(s30, v);
            if (k <= 7)  s7  = f4add(s7, v);
        }
    }

    const float inv7  = 1.0f / 7.0f;
    const float inv30 = 1.0f / 30.0f;
    const float inv90 = 1.0f / 90.0f;

    int i = r0;
    const int end = r0 + ROWS;

    if (r0 < 90) {
        // Careful region (rows < 90): expanding-mean divisors, zero-padded lags.
        // Only tiles 0..2 run any of this.
        int cend = (end < 90) ? end : 90;
        for (; i < cend; i++) {
            float4 v = xc[i * XR4];
            s7 = f4add(s7, v); s30 = f4add(s30, v); s90 = f4add(s90, v);
            if (i >= 7)  s7  = f4sub(s7,  __ldcg(&xc[(i - 7)  * XR4]));
            if (i >= 30) s30 = f4sub(s30, __ldcg(&xc[(i - 30) * XR4]));
            float r7  = (i >= 6)  ? inv7  : 1.0f / (float)(i + 1);
            float r30 = (i >= 29) ? inv30 : 1.0f / (float)(i + 1);
            float r90 = 1.0f / (float)(i + 1);  // i<=89; at i==89 windowed /90 == /(i+1)
            float4* o = oc + i * OR4;
            __stcs(o,            v);
            __stcs(o + XR4,      f4scale(s7,  r7));
            __stcs(o + 2 * XR4,  f4scale(s30, r30));
            __stcs(o + 3 * XR4,  f4scale(s90, r90));
        }
    }

    // Fast path: steady-state sliding windows.
    #pragma unroll 2
    for (; i < end; i++) {
        float4 v   = xc[i * XR4];
        float4 v7  = __ldcg(&xc[(i - 7)  * XR4]);
        float4 v30 = __ldcg(&xc[(i - 30) * XR4]);
        float4 v90 = __ldcg(&xc[(i - 90) * XR4]);
        s7  = f4add(s7,  f4sub(v, v7));
        s30 = f4add(s30, f4sub(v, v30));
        s90 = f4add(s90, f4sub(v, v90));
        float4* o = oc + i * OR4;
        __stcs(o,            v);
        __stcs(o + XR4,      f4scale(s7,  inv7));
        __stcs(o + 2 * XR4,  f4scale(s30, inv30));
        __stcs(o + 3 * XR4,  f4scale(s90, inv90));
    }
}

extern "C" void kernel_launch(void* const* d_in, const int* in_sizes, int n_in,
                              void* d_out, int out_size) {
    const float* x  = (const float*)d_in[0];
    float*      out = (float*)d_out;
    int n_tiles  = T_TOTAL / ROWS;                    // 8192
    int n_blocks = n_tiles / TILES_PER_BLOCK;         // 1024
    ma_kernel<<<n_blocks, 128>>>(x, out);
}

// round 8
// speedup vs baseline: 1.2822x; 1.2822x over previous
#include <cuda_runtime.h>

#define T_TOTAL    262144
#define NF         64
#define NF2        (NF / 2)        // 32 float2 per x row
#define ONF2       (4 * NF / 2)    // 128 float2 per out row
#define TILE_ROWS  128
#define HALO       90
#define SROWS      (TILE_ROWS + HALO)      // 218
#define SMEM_F4    (SROWS * NF / 4)        // 3488 float4
#define SMEM_BYTES (SROWS * NF * 4)        // 55808 B
#define THREADS    256
#define GROUPS     8
#define GROUP_ROWS (TILE_ROWS / GROUPS)    // 16

__device__ __forceinline__ float2 f2add(float2 a, float2 b) {
    return make_float2(a.x + b.x, a.y + b.y);
}
__device__ __forceinline__ float2 f2sub(float2 a, float2 b) {
    return make_float2(a.x - b.x, a.y - b.y);
}
__device__ __forceinline__ float2 f2scale(float2 a, float s) {
    return make_float2(a.x * s, a.y * s);
}

__global__ void __launch_bounds__(THREADS, 4)
ma_kernel(const float* __restrict__ x, float* __restrict__ out) {
    extern __shared__ float4 sm4[];
    float2* sm2 = (float2*)sm4;              // [SROWS][NF2] row stride NF2

    const int t     = threadIdx.x;
    const int blk   = blockIdx.x;
    const int base  = blk * TILE_ROWS - HALO;   // global row of smem row 0

    // ---- Phase 1: stream tile + halo into smem (float4, fully coalesced) ----
    const float4* x4 = (const float4*)x;     // row stride NF/4 = 16
    #pragma unroll 4
    for (int idx = t; idx < SMEM_F4; idx += THREADS) {
        int s  = idx >> 4;                    // smem row
        int gr = base + s;                    // global row
        float4 v;
        if (gr >= 0) {
            v = __ldcg(&x4[idx + base * (NF / 4)]);
        } else {
            v = make_float4(0.f, 0.f, 0.f, 0.f);   // zero-pad rows < 0
        }
        sm4[idx] = v;
    }
    __syncthreads();

    // ---- Phase 2: sliding windows out of smem ----
    const int p  = t & 31;                    // col-pair 0..31
    const int g  = t >> 5;                    // row group 0..7
    const int lr0 = HALO + g * GROUP_ROWS;    // first smem row of my strip
    const int gr0 = blk * TILE_ROWS + g * GROUP_ROWS;  // its global row

    float2 s7  = make_float2(0.f, 0.f);
    float2 s30 = s7, s90 = s7;

    // Build entry window sums from the 90 rows preceding the strip (in smem;
    // zero-padded for block 0, so sums are exact).
    #pragma unroll 6
    for (int k = 1; k <= HALO; k++) {
        float2 v = sm2[(lr0 - k) * NF2 + p];
        s90 = f2add(s90, v);
        if (k <= 30) s30 = f2add(s30, v);
        if (k <= 7)  s7  = f2add(s7, v);
    }

    const float inv7  = 1.0f / 7.0f;
    const float inv30 = 1.0f / 30.0f;
    const float inv90 = 1.0f / 90.0f;

    float2* oc = (float2*)out + p;           // row stride ONF2

    if (blk == 0) {
        // Careful region: rows < 90 use expanding divisors. Zero-padded halo
        // makes the window sums equal the cumsum automatically.
        for (int j = 0; j < GROUP_ROWS; j++) {
            int lr = lr0 + j;
            int gi = gr0 + j;
            float2 v   = sm2[lr * NF2 + p];
            float2 v7  = sm2[(lr - 7)  * NF2 + p];
            float2 v30 = sm2[(lr - 30) * NF2 + p];
            float2 v90 = sm2[(lr - 90) * NF2 + p];
            s7  = f2add(s7,  f2sub(v, v7));
            s30 = f2add(s30, f2sub(v, v30));
            s90 = f2add(s90, f2sub(v, v90));
            float rn  = 1.0f / (float)(gi + 1);
            float r7  = (gi >= 6)  ? inv7  : rn;
            float r30 = (gi >= 29) ? inv30 : rn;
            float r90 = (gi >= 89) ? inv90 : rn;
            float2* o = oc + gi * ONF2;
            __stcs(o,           v);
            __stcs(o + NF2,     f2scale(s7,  r7));
            __stcs(o + 2 * NF2, f2scale(s30, r30));
            __stcs(o + 3 * NF2, f2scale(s90, r90));
        }
    } else {
        #pragma unroll 4
        for (int j = 0; j < GROUP_ROWS; j++) {
            int lr = lr0 + j;
            int gi = gr0 + j;
            float2 v   = sm2[lr * NF2 + p];
            float2 v7  = sm2[(lr - 7)  * NF2 + p];
            float2 v30 = sm2[(lr - 30) * NF2 + p];
            float2 v90 = sm2[(lr - 90) * NF2 + p];
            s7  = f2add(s7,  f2sub(v, v7));
            s30 = f2add(s30, f2sub(v, v30));
            s90 = f2add(s90, f2sub(v, v90));
            float2* o = oc + gi * ONF2;
            __stcs(o,           v);
            __stcs(o + NF2,     f2scale(s7,  inv7));
            __stcs(o + 2 * NF2, f2scale(s30, inv30));
            __stcs(o + 3 * NF2, f2scale(s90, inv90));
        }
    }
}

extern "C" void kernel_launch(void* const* d_in, const int* in_sizes, int n_in,
                              void* d_out, int out_size) {
    const float* x  = (const float*)d_in[0];
    float*      out = (float*)d_out;
    static int attr_set = 0;
    if (!attr_set) {
        cudaFuncSetAttribute(ma_kernel,
                             cudaFuncAttributeMaxDynamicSharedMemorySize,
                             SMEM_BYTES);
        attr_set = 1;
    }
    int n_blocks = T_TOTAL / TILE_ROWS;      // 2048
    ma_kernel<<<n_blocks, THREADS, SMEM_BYTES>>>(x, out);
}

// round 9
// speedup vs baseline: 1.3165x; 1.0268x over previous
#include <cuda_runtime.h>

#define T_TOTAL    262144
#define NF         64
#define TILE_ROWS  128
#define HALO       90
#define SROWS      (TILE_ROWS + HALO)      // 218
#define SMEM_F4    (SROWS * NF / 4)        // 3488
#define SMEM_BYTES (SROWS * NF * 4)        // 55808
#define THREADS    256
#define GROUPS     4
#define GROUP_ROWS (TILE_ROWS / GROUPS)    // 32

__global__ void __launch_bounds__(THREADS, 4)
ma_kernel(const float* __restrict__ x, float* __restrict__ out) {
    extern __shared__ float4 sm4[];
    float* sm = (float*)sm4;                    // [SROWS][NF]

    const int t    = threadIdx.x;
    const int blk  = blockIdx.x;
    const int base = blk * TILE_ROWS - HALO;    // global row of smem row 0

    // ---- Phase 1: stream tile + halo into smem (float4, coalesced) ----
    const float4* x4 = (const float4*)x;        // row stride NF/4 = 16
    #pragma unroll 4
    for (int idx = t; idx < SMEM_F4; idx += THREADS) {
        int gr = base + (idx >> 4);
        float4 v;
        if (gr >= 0) {
            v = __ldcg(&x4[idx + base * (NF / 4)]);
        } else {
            v = make_float4(0.f, 0.f, 0.f, 0.f);   // zero-pad rows < 0
        }
        sm4[idx] = v;
    }
    __syncthreads();

    // ---- Phase 2: one column per thread, 32-row strip per group ----
    const int c   = t & (NF - 1);               // column 0..63 (lane-contiguous)
    const int g   = t >> 6;                     // group 0..3
    const int lr0 = HALO + g * GROUP_ROWS;      // first smem row of strip
    const int gr0 = blk * TILE_ROWS + g * GROUP_ROWS;

    float s7 = 0.f, s30 = 0.f, s90 = 0.f;

    // Entry sums over the 90 rows preceding the strip (zero-padded for blk 0).
    #pragma unroll 10
    for (int k = 1; k <= HALO; k++) {
        float v = sm[(lr0 - k) * NF + c];
        s90 += v;
        if (k <= 30) s30 += v;
        if (k <= 7)  s7  += v;
    }

    const float inv7  = 1.0f / 7.0f;
    const float inv30 = 1.0f / 30.0f;
    const float inv90 = 1.0f / 90.0f;

    float* oc = out + c;                        // out row stride 4*NF
    float hist[GROUP_ROWS];

    if (blk == 0) {
        // Careful region: rows < 90 use expanding divisors; zero-padded halo
        // makes the sliding sums equal the cumsum automatically.
        #pragma unroll
        for (int j = 0; j < GROUP_ROWS; j++) {
            int lr = lr0 + j;
            int gi = gr0 + j;
            float v   = sm[lr * NF + c];
            hist[j] = v;
            float v7  = (j >= 7)  ? hist[j - 7]  : sm[(lr - 7)  * NF + c];
            float v30 = (j >= 30) ? hist[j - 30] : sm[(lr - 30) * NF + c];
            float v90 = sm[(lr - 90) * NF + c];
            s7 += v - v7; s30 += v - v30; s90 += v - v90;
            float rn  = 1.0f / (float)(gi + 1);
            float r7  = (gi >= 6)  ? inv7  : rn;
            float r30 = (gi >= 29) ? inv30 : rn;
            float r90 = (gi >= 89) ? inv90 : rn;
            float* o = oc + gi * (4 * NF);
            __stcs(o,          v);
            __stcs(o + NF,     s7  * r7);
            __stcs(o + 2 * NF, s30 * r30);
            __stcs(o + 3 * NF, s90 * r90);
        }
    } else {
        #pragma unroll
        for (int j = 0; j < GROUP_ROWS; j++) {
            int lr = lr0 + j;
            int gi = gr0 + j;
            float v   = sm[lr * NF + c];
            hist[j] = v;
            float v7  = (j >= 7)  ? hist[j - 7]  : sm[(lr - 7)  * NF + c];
            float v30 = (j >= 30) ? hist[j - 30] : sm[(lr - 30) * NF + c];
            float v90 = sm[(lr - 90) * NF + c];
            s7 += v - v7; s30 += v - v30; s90 += v - v90;
            float* o = oc + gi * (4 * NF);
            __stcs(o,          v);
            __stcs(o + NF,     s7  * inv7);
            __stcs(o + 2 * NF, s30 * inv30);
            __stcs(o + 3 * NF, s90 * inv90);
        }
    }
}

extern "C" void kernel_launch(void* const* d_in, const int* in_sizes, int n_in,
                              void* d_out, int out_size) {
    const float* x  = (const float*)d_in[0];
    float*      out = (float*)d_out;
    static int attr_set = 0;
    if (!attr_set) {
        cudaFuncSetAttribute(ma_kernel,
                             cudaFuncAttributeMaxDynamicSharedMemorySize,
                             SMEM_BYTES);
        attr_set = 1;
    }
    int n_blocks = T_TOTAL / TILE_ROWS;         // 2048
    ma_kernel<<<n_blocks, THREADS, SMEM_BYTES>>>(x, out);
}